// round 1
// baseline (speedup 1.0000x reference)
#include <cuda_runtime.h>
#include <climits>

// Decoder_predict: batched greedy goals-NMS.
// B=256 samples, N=4096 candidates, T=30 traj steps, K=6 selections.
// scores = class * centerness; greedy NMS with threshold^2 = 4.0.
//
// Equivalence used: the sorted-scan greedy NMS == K rounds of
// "argmax over candidates not conflicting with current selected set".
// Tie-break on equal score: lower original index (matches stable argsort).

#define NMS_B 256
#define NMS_N 4096
#define NMS_T 30
#define NMS_K 6
#define NMS_THREADS 256
#define PER_THREAD (NMS_N / NMS_THREADS)   // 16
#define NMS_THR2 4.0f

__global__ __launch_bounds__(NMS_THREADS)
void nms_goals_kernel(const float* __restrict__ coord,   // [B,1,N,2]
                      const float* __restrict__ cls,     // [B,1,N]
                      const float* __restrict__ traj,    // [B,1,N,T,2]
                      const float* __restrict__ cent,    // [B,1,N]
                      float* __restrict__ out)           // trajs | probs | goals
{
    const int b   = blockIdx.x;
    const int tid = threadIdx.x;

    const float2* cptr = (const float2*)(coord + (size_t)b * NMS_N * 2);
    const float*  sc   = cls  + (size_t)b * NMS_N;
    const float*  ce   = cent + (size_t)b * NMS_N;

    // Register-resident candidate set: 16 per thread, strided layout so
    // global loads are fully coalesced.
    float lx[PER_THREAD], ly[PER_THREAD], ls[PER_THREAD];
    unsigned int alive = 0xFFFFu;  // 16 bits, one per local candidate

#pragma unroll
    for (int j = 0; j < PER_THREAD; j++) {
        const int i = tid + j * NMS_THREADS;
        const float2 c = cptr[i];
        lx[j] = c.x;
        ly[j] = c.y;
        ls[j] = sc[i] * ce[i];
    }

    __shared__ float red_s[NMS_THREADS];
    __shared__ int   red_i[NMS_THREADS];
    __shared__ float sel_x[NMS_K], sel_y[NMS_K], sel_s[NMS_K];
    __shared__ int   sel_i[NMS_K];

    for (int r = 0; r < NMS_K; r++) {
        // Per-thread argmax over still-alive candidates (tie -> lower index).
        float best = -1e30f;
        int   bi   = INT_MAX;
#pragma unroll
        for (int j = 0; j < PER_THREAD; j++) {
            if (alive & (1u << j)) {
                const int i = tid + j * NMS_THREADS;
                const float s = ls[j];
                if (s > best || (s == best && i < bi)) { best = s; bi = i; }
            }
        }
        red_s[tid] = best;
        red_i[tid] = bi;
        __syncthreads();

        // Shared-memory tree reduction for block argmax.
        for (int off = NMS_THREADS / 2; off > 0; off >>= 1) {
            if (tid < off) {
                const float os = red_s[tid + off];
                const int   oi = red_i[tid + off];
                if (os > red_s[tid] || (os == red_s[tid] && oi < red_i[tid])) {
                    red_s[tid] = os;
                    red_i[tid] = oi;
                }
            }
            __syncthreads();
        }

        if (tid == 0) {
            if (red_s[0] <= -1e29f) {
                sel_i[r] = -1;  // no candidate left (fallback slot)
                sel_s[r] = 0.0f; sel_x[r] = 0.0f; sel_y[r] = 0.0f;
            } else {
                const int wi = red_i[0];
                const float2 c = cptr[wi];   // L2 hit; cheap
                sel_x[r] = c.x;
                sel_y[r] = c.y;
                sel_s[r] = red_s[0];
                sel_i[r] = wi;
            }
        }
        __syncthreads();

        // Suppress candidates within threshold of the newest selection.
        // (The selected point itself has d2 = 0 and is suppressed too.)
        if (sel_i[r] >= 0) {
            const float px = sel_x[r];
            const float py = sel_y[r];
#pragma unroll
            for (int j = 0; j < PER_THREAD; j++) {
                if (alive & (1u << j)) {
                    const float dx = lx[j] - px;
                    const float dy = ly[j] - py;
                    if (dx * dx + dy * dy < NMS_THR2) alive &= ~(1u << j);
                }
            }
        }
        __syncthreads();
    }

    // ---- Write outputs. Layout: pred_trajs [B,K,T,2] | probs [B,K] | goals [B,K,2]
    float* out_traj = out;
    float* out_prob = out + (size_t)NMS_B * NMS_K * NMS_T * 2;
    float* out_goal = out_prob + (size_t)NMS_B * NMS_K;

    if (tid < NMS_K) {
        const int  k     = tid;
        const bool valid = (sel_i[k] >= 0);
        // Fallback slot semantics: sel_idx stays 0 -> sorted-first point's
        // score/traj (= round-0 selection), goal stays (0,0).
        out_prob[(size_t)b * NMS_K + k]            = valid ? sel_s[k] : sel_s[0];
        out_goal[((size_t)b * NMS_K + k) * 2 + 0]  = valid ? sel_x[k] : 0.0f;
        out_goal[((size_t)b * NMS_K + k) * 2 + 1]  = valid ? sel_y[k] : 0.0f;
    }

    // Gather selected trajectories: K * T * 2 = 360 floats per batch.
    for (int e = tid; e < NMS_K * NMS_T * 2; e += NMS_THREADS) {
        const int k   = e / (NMS_T * 2);
        const int rem = e % (NMS_T * 2);
        const int src = (sel_i[k] >= 0) ? sel_i[k] : sel_i[0];
        out_traj[((size_t)b * NMS_K + k) * (NMS_T * 2) + rem] =
            traj[((size_t)b * NMS_N + src) * (NMS_T * 2) + rem];
    }
}

extern "C" void kernel_launch(void* const* d_in, const int* in_sizes, int n_in,
                              void* d_out, int out_size) {
    const float* coord = (const float*)d_in[0];  // outputs_coord     [B,1,N,2]
    const float* cls   = (const float*)d_in[1];  // outputs_class     [B,1,N]
    const float* traj  = (const float*)d_in[2];  // outputs_traj      [B,1,N,T,2]
    const float* cent  = (const float*)d_in[3];  // outputs_centerness[B,1,N]
    float* out = (float*)d_out;

    nms_goals_kernel<<<NMS_B, NMS_THREADS>>>(coord, cls, traj, cent, out);
}

// round 2
// speedup vs baseline: 1.4207x; 1.4207x over previous
#include <cuda_runtime.h>

// Decoder_predict: batched greedy goals-NMS.
// B=256, N=4096, T=30, K=6. scores = class * centerness, thr^2 = 4.0.
// Greedy sorted-scan NMS == K rounds of argmax over non-suppressed candidates.
//
// V2: 512 threads/CTA (2 CTAs/SM -> single wave), float4/float2 vector loads
// (MLP ~12 per thread), shuffle-based argmax with packed u64 keys
// ((score_bits<<32)|~idx : positive-float bits are order-monotone, ~idx gives
// lower-index tie-break, packed==0 means suppressed/none).

#define NMS_B 256
#define NMS_N 4096
#define NMS_T 30
#define NMS_K 6
#define NMS_THREADS 512
#define PER_THREAD (NMS_N / NMS_THREADS)   // 8
#define NMS_THR2 4.0f

__global__ __launch_bounds__(NMS_THREADS, 2)
void nms_goals_kernel(const float* __restrict__ coord,   // [B,1,N,2]
                      const float* __restrict__ cls,     // [B,1,N]
                      const float* __restrict__ traj,    // [B,1,N,T,2]
                      const float* __restrict__ cent,    // [B,1,N]
                      float* __restrict__ out)           // trajs | probs | goals
{
    const int b    = blockIdx.x;
    const int tid  = threadIdx.x;
    const int wid  = tid >> 5;
    const int lane = tid & 31;

    const float4* c4 = (const float4*)(coord + (size_t)b * NMS_N * 2);
    const float2* s2 = (const float2*)(cls   + (size_t)b * NMS_N);
    const float2* e2 = (const float2*)(cent  + (size_t)b * NMS_N);
    const float2* cptr = (const float2*)(coord + (size_t)b * NMS_N * 2);

    // Candidate j (j in [0,8)) of this thread is global index:
    //   i = 2*(tid + (j>>1)*512) + (j&1)
    float x[PER_THREAD], y[PER_THREAD];
    unsigned long long pk[PER_THREAD];

    // Issue all wide loads up front (independent -> high MLP).
    float4 cv[4];
    float2 av[4], dv[4];
#pragma unroll
    for (int k = 0; k < 4; k++) cv[k] = c4[tid + k * NMS_THREADS];
#pragma unroll
    for (int k = 0; k < 4; k++) av[k] = s2[tid + k * NMS_THREADS];
#pragma unroll
    for (int k = 0; k < 4; k++) dv[k] = e2[tid + k * NMS_THREADS];

#pragma unroll
    for (int k = 0; k < 4; k++) {
        const unsigned int i0 = 2u * (unsigned)(tid + k * NMS_THREADS);
        x[2*k]   = cv[k].x;  y[2*k]   = cv[k].y;
        x[2*k+1] = cv[k].z;  y[2*k+1] = cv[k].w;
        const float sA = av[k].x * dv[k].x;
        const float sB = av[k].y * dv[k].y;
        pk[2*k]   = ((unsigned long long)__float_as_uint(sA) << 32) | (unsigned)(~i0);
        pk[2*k+1] = ((unsigned long long)__float_as_uint(sB) << 32) | (unsigned)(~(i0 + 1u));
    }

    __shared__ unsigned long long warp_best[NMS_THREADS / 32];
    __shared__ float sel_x[NMS_K], sel_y[NMS_K], sel_s[NMS_K];
    __shared__ int   sel_i[NMS_K];

    for (int r = 0; r < NMS_K; r++) {
        // Per-thread max over 8 packed keys.
        unsigned long long best = pk[0];
#pragma unroll
        for (int j = 1; j < PER_THREAD; j++) best = max(best, pk[j]);

        // Warp max via shuffles.
#pragma unroll
        for (int off = 16; off > 0; off >>= 1)
            best = max(best, __shfl_down_sync(0xFFFFFFFFu, best, off));
        if (lane == 0) warp_best[wid] = best;
        __syncthreads();

        // First warp reduces the 16 warp winners; lane 0 publishes selection.
        if (wid == 0) {
            unsigned long long v = (lane < NMS_THREADS / 32) ? warp_best[lane] : 0ULL;
#pragma unroll
            for (int off = 8; off > 0; off >>= 1)
                v = max(v, __shfl_down_sync(0xFFFFFFFFu, v, off));
            if (lane == 0) {
                if (v == 0ULL) {
                    sel_i[r] = -1; sel_s[r] = 0.0f;
                    sel_x[r] = 0.0f; sel_y[r] = 0.0f;
                } else {
                    const int wi = (int)(~(unsigned int)(v & 0xFFFFFFFFu));
                    const float2 c = cptr[wi];     // L2 hit
                    sel_i[r] = wi;
                    sel_s[r] = __uint_as_float((unsigned int)(v >> 32));
                    sel_x[r] = c.x;
                    sel_y[r] = c.y;
                }
            }
        }
        __syncthreads();

        // Suppress everything within thr of the newest selection (incl. itself).
        if (sel_i[r] >= 0) {
            const float px = sel_x[r];
            const float py = sel_y[r];
#pragma unroll
            for (int j = 0; j < PER_THREAD; j++) {
                const float dx = x[j] - px;
                const float dy = y[j] - py;
                if (dx * dx + dy * dy < NMS_THR2) pk[j] = 0ULL;
            }
        }
        // No barrier needed here: next round's first barrier orders the
        // register updates (pk is thread-private; warp_best rewritten after
        // the __syncthreads above... but warp_best[wid] write in next round
        // races with warp0's read this round -> keep a barrier.
        __syncthreads();
    }

    // ---- Outputs. Layout: pred_trajs [B,K,T,2] | probs [B,K] | goals [B,K,2]
    float* out_traj = out;
    float* out_prob = out + (size_t)NMS_B * NMS_K * NMS_T * 2;
    float* out_goal = out_prob + (size_t)NMS_B * NMS_K;

    if (tid < NMS_K) {
        const int  k     = tid;
        const bool valid = (sel_i[k] >= 0);
        // Fallback slot semantics: sel_idx stays 0 -> sorted-first point's
        // score/traj (= round-0 selection), goal stays (0,0).
        out_prob[(size_t)b * NMS_K + k]           = valid ? sel_s[k] : sel_s[0];
        out_goal[((size_t)b * NMS_K + k) * 2 + 0] = valid ? sel_x[k] : 0.0f;
        out_goal[((size_t)b * NMS_K + k) * 2 + 1] = valid ? sel_y[k] : 0.0f;
    }

    // Gather selected trajectories: K * T * 2 = 360 floats per batch.
    for (int e = tid; e < NMS_K * NMS_T * 2; e += NMS_THREADS) {
        const int k   = e / (NMS_T * 2);
        const int rem = e % (NMS_T * 2);
        const int src = (sel_i[k] >= 0) ? sel_i[k] : sel_i[0];
        out_traj[((size_t)b * NMS_K + k) * (NMS_T * 2) + rem] =
            traj[((size_t)b * NMS_N + src) * (NMS_T * 2) + rem];
    }
}

extern "C" void kernel_launch(void* const* d_in, const int* in_sizes, int n_in,
                              void* d_out, int out_size) {
    const float* coord = (const float*)d_in[0];  // outputs_coord     [B,1,N,2]
    const float* cls   = (const float*)d_in[1];  // outputs_class     [B,1,N]
    const float* traj  = (const float*)d_in[2];  // outputs_traj      [B,1,N,T,2]
    const float* cent  = (const float*)d_in[3];  // outputs_centerness[B,1,N]
    float* out = (float*)d_out;

    nms_goals_kernel<<<NMS_B, NMS_THREADS>>>(coord, cls, traj, cent, out);
}